// round 7
// baseline (speedup 1.0000x reference)
#include <cuda_runtime.h>
#include <cuda_fp16.h>

#define N_NODES 100000
#define E_EDGES 1600000
#define D 128

// ---------------- scratch (static device globals; no runtime alloc) ---------
__device__ __half g_feat_h[N_NODES * D];  // projected features fp16 (25.6 MB)
__device__ float  g_wl[D];                // W @ attn_l
__device__ float  g_wr[D];                // W @ attn_r
__device__ float  g_el[N_NODES];          // src attention logits (fp32-exact)
__device__ float  g_er[N_NODES];          // dst attention logits
__device__ int    g_cnt[N_NODES];         // in-degree histogram (zeroed by scanC)
__device__ int    g_off[N_NODES + 1];     // CSR offsets (off[N]=E)
__device__ int    g_cur[N_NODES];         // scatter cursors
__device__ int2   g_sedge[E_EDGES];       // CSR slot: {src, exp-weight bits}

#define SCAN_BS 512
#define NPART ((N_NODES + SCAN_BS - 1) / SCAN_BS)   // 196
__device__ int g_part[NPART];
__device__ int g_pbase[NPART];

// ---------------- packed f32x2 helpers (sm_103a FFMA2) ----------------------
__device__ __forceinline__ unsigned long long pack2(float lo, float hi) {
    unsigned long long r;
    asm("mov.b64 %0, {%1,%2};" : "=l"(r) : "f"(lo), "f"(hi));
    return r;
}
__device__ __forceinline__ void unpack2(unsigned long long v, float& lo, float& hi) {
    asm("mov.b64 {%0,%1}, %2;" : "=f"(lo), "=f"(hi) : "l"(v));
}
__device__ __forceinline__ unsigned long long ffma2(unsigned long long a,
                                                    unsigned long long b,
                                                    unsigned long long c) {
    unsigned long long d;
    asm("fma.rn.f32x2 %0, %1, %2, %3;" : "=l"(d) : "l"(a), "l"(b), "l"(c));
    return d;
}
__device__ __forceinline__ float2 h2tof2(unsigned int u) {
    __half2 h;
    *reinterpret_cast<unsigned int*>(&h) = u;
    return __half22float2(h);
}

// ---------------- K0: wl = W @ attn_l, wr = W @ attn_r ----------------------
__global__ void __launch_bounds__(256)
wlr_kernel(const float* __restrict__ W,
           const float* __restrict__ attn_l, const float* __restrict__ attn_r) {
    const int t = threadIdx.x;           // 0..255
    const int k = t & 127;               // W row
    const float* v = (t < 128) ? attn_l : attn_r;
    float s = 0.f;
    #pragma unroll 8
    for (int j = 0; j < D; j++)
        s = fmaf(__ldg(&W[k * D + j]), __ldg(&v[j]), s);
    if (t < 128) g_wl[k] = s; else g_wr[k] = s;
}

// ---------------- K1: feat = h @ W  (16 rows/block, packed FFMA2) -----------
__global__ void __launch_bounds__(128)
gemm_kernel(const float* __restrict__ h, const float* __restrict__ W) {
    __shared__ float4 hs4[D][4];
    const int t = threadIdx.x;              // output column
    const int row0 = blockIdx.x * 16;

    {
        float tmp[16];
        #pragma unroll
        for (int r = 0; r < 16; r++)
            tmp[r] = h[(row0 + r) * D + t];
        #pragma unroll
        for (int q = 0; q < 4; q++)
            hs4[t][q] = make_float4(tmp[4*q], tmp[4*q+1], tmp[4*q+2], tmp[4*q+3]);
    }
    __syncthreads();

    unsigned long long acc2[8];
    #pragma unroll
    for (int j = 0; j < 8; j++) acc2[j] = 0ull;

    #pragma unroll 4
    for (int k = 0; k < D; k++) {
        const float wv = __ldg(&W[k * D + t]);
        const unsigned long long w2 = pack2(wv, wv);
        #pragma unroll
        for (int q = 0; q < 4; q++) {
            const float4 v = hs4[k][q];
            acc2[2*q]   = ffma2(pack2(v.x, v.y), w2, acc2[2*q]);
            acc2[2*q+1] = ffma2(pack2(v.z, v.w), w2, acc2[2*q+1]);
        }
    }

    #pragma unroll
    for (int j = 0; j < 8; j++) {
        float lo, hi;
        unpack2(acc2[j], lo, hi);
        g_feat_h[(row0 + 2*j)     * D + t] = __float2half(lo);
        g_feat_h[(row0 + 2*j + 1) * D + t] = __float2half(hi);
    }
}

// ---------------- K2: el/er = h @ wl, h @ wr  (warp per node, fp32) ---------
__global__ void __launch_bounds__(256)
elr_kernel(const float* __restrict__ h) {
    const int warp = (blockIdx.x * blockDim.x + threadIdx.x) >> 5;
    const int lane = threadIdx.x & 31;
    if (warp >= N_NODES) return;

    const float4 f  = __ldg(&reinterpret_cast<const float4*>(h)[warp * 32 + lane]);
    const float4 al = reinterpret_cast<const float4*>(g_wl)[lane];
    const float4 ar = reinterpret_cast<const float4*>(g_wr)[lane];
    float sl = f.x * al.x + f.y * al.y + f.z * al.z + f.w * al.w;
    float sr = f.x * ar.x + f.y * ar.y + f.z * ar.z + f.w * ar.w;
    #pragma unroll
    for (int o = 16; o; o >>= 1) {
        sl += __shfl_down_sync(0xffffffffu, sl, o);
        sr += __shfl_down_sync(0xffffffffu, sr, o);
    }
    if (lane == 0) { g_el[warp] = sl; g_er[warp] = sr; }
}

// ---------------- K3: in-degree histogram -----------------------------------
__global__ void __launch_bounds__(256)
hist_kernel(const int* __restrict__ dst) {
    const int e = blockIdx.x * blockDim.x + threadIdx.x;
    if (e < E_EDGES) atomicAdd(&g_cnt[dst[e]], 1);
}

// ---------------- K4a/b/c: hierarchical exclusive scan ----------------------
__global__ void __launch_bounds__(SCAN_BS)
scanA_kernel() {
    __shared__ int sh[SCAN_BS];
    const int t = threadIdx.x;
    const int i = blockIdx.x * SCAN_BS + t;
    sh[t] = (i < N_NODES) ? g_cnt[i] : 0;
    __syncthreads();
    #pragma unroll
    for (int o = SCAN_BS / 2; o; o >>= 1) {
        if (t < o) sh[t] += sh[t + o];
        __syncthreads();
    }
    if (t == 0) g_part[blockIdx.x] = sh[0];
}

__global__ void __launch_bounds__(256)
scanB_kernel() {
    __shared__ int sh[256];
    const int t = threadIdx.x;
    const int v = (t < NPART) ? g_part[t] : 0;
    sh[t] = v;
    __syncthreads();
    for (int o = 1; o < 256; o <<= 1) {
        const int x = (t >= o) ? sh[t - o] : 0;
        __syncthreads();
        sh[t] += x;
        __syncthreads();
    }
    if (t < NPART) g_pbase[t] = sh[t] - v;       // exclusive
}

__global__ void __launch_bounds__(SCAN_BS)
scanC_kernel() {
    __shared__ int sh[SCAN_BS];
    const int t = threadIdx.x;
    const int i = blockIdx.x * SCAN_BS + t;
    const int c = (i < N_NODES) ? g_cnt[i] : 0;
    sh[t] = c;
    __syncthreads();
    for (int o = 1; o < SCAN_BS; o <<= 1) {
        const int x = (t >= o) ? sh[t - o] : 0;
        __syncthreads();
        sh[t] += x;
        __syncthreads();
    }
    if (i < N_NODES) {
        const int off = g_pbase[blockIdx.x] + sh[t] - c;   // exclusive
        g_off[i] = off;
        g_cur[i] = off;
        g_cnt[i] = 0;                       // restore invariant for next replay
    }
    if (blockIdx.x == 0 && t == 0) g_off[N_NODES] = E_EDGES;
}

// ---------------- K5: fused edge score + CSR scatter ------------------------
__global__ void __launch_bounds__(256)
scatter_kernel(const int* __restrict__ src, const int* __restrict__ dst) {
    const int e = blockIdx.x * blockDim.x + threadIdx.x;
    if (e >= E_EDGES) return;
    const int s = src[e];
    const int d = dst[e];
    float x = g_el[s] + g_er[d];
    x = (x > 0.f) ? x : 0.2f * x;            // leaky relu
    const float ex = __expf(x);              // |x| small: no max-shift needed
    const int idx = atomicAdd(&g_cur[d], 1);
    g_sedge[idx] = make_int2(s, __float_as_int(ex));
}

// ---------------- K6: aggregation — warp per node, fp16 gather, unroll 4 ----
__global__ void __launch_bounds__(256)
agg_kernel(float* __restrict__ out) {
    const int warp = (blockIdx.x * blockDim.x + threadIdx.x) >> 5;
    const int lane = threadIdx.x & 31;
    if (warp >= N_NODES) return;

    const int beg = g_off[warp];
    const int end = g_off[warp + 1];

    const uint2* __restrict__ featv = reinterpret_cast<const uint2*>(g_feat_h);

    float4 acc = make_float4(0.f, 0.f, 0.f, 0.f);
    float den = 0.f;
    int j = beg;
    for (; j + 4 <= end; j += 4) {
        const int2 p0 = g_sedge[j];
        const int2 p1 = g_sedge[j + 1];
        const int2 p2 = g_sedge[j + 2];
        const int2 p3 = g_sedge[j + 3];
        const uint2 v0 = __ldg(&featv[p0.x * 32 + lane]);
        const uint2 v1 = __ldg(&featv[p1.x * 32 + lane]);
        const uint2 v2 = __ldg(&featv[p2.x * 32 + lane]);
        const uint2 v3 = __ldg(&featv[p3.x * 32 + lane]);
        const float w0 = __int_as_float(p0.y);
        const float w1 = __int_as_float(p1.y);
        const float w2 = __int_as_float(p2.y);
        const float w3 = __int_as_float(p3.y);
        den += (w0 + w1) + (w2 + w3);
        const float2 a0 = h2tof2(v0.x), b0 = h2tof2(v0.y);
        const float2 a1 = h2tof2(v1.x), b1 = h2tof2(v1.y);
        const float2 a2 = h2tof2(v2.x), b2 = h2tof2(v2.y);
        const float2 a3 = h2tof2(v3.x), b3 = h2tof2(v3.y);
        acc.x = fmaf(w0, a0.x, acc.x); acc.y = fmaf(w0, a0.y, acc.y);
        acc.z = fmaf(w0, b0.x, acc.z); acc.w = fmaf(w0, b0.y, acc.w);
        acc.x = fmaf(w1, a1.x, acc.x); acc.y = fmaf(w1, a1.y, acc.y);
        acc.z = fmaf(w1, b1.x, acc.z); acc.w = fmaf(w1, b1.y, acc.w);
        acc.x = fmaf(w2, a2.x, acc.x); acc.y = fmaf(w2, a2.y, acc.y);
        acc.z = fmaf(w2, b2.x, acc.z); acc.w = fmaf(w2, b2.y, acc.w);
        acc.x = fmaf(w3, a3.x, acc.x); acc.y = fmaf(w3, a3.y, acc.y);
        acc.z = fmaf(w3, b3.x, acc.z); acc.w = fmaf(w3, b3.y, acc.w);
    }
    for (; j < end; j++) {
        const int2 p = g_sedge[j];
        const uint2 v = __ldg(&featv[p.x * 32 + lane]);
        const float w = __int_as_float(p.y);
        den += w;
        const float2 a = h2tof2(v.x), b = h2tof2(v.y);
        acc.x = fmaf(w, a.x, acc.x); acc.y = fmaf(w, a.y, acc.y);
        acc.z = fmaf(w, b.x, acc.z); acc.w = fmaf(w, b.y, acc.w);
    }
    const float inv = 1.f / fmaxf(den, 1e-9f);
    acc.x *= inv; acc.y *= inv; acc.z *= inv; acc.w *= inv;
    reinterpret_cast<float4*>(out)[warp * 32 + lane] = acc;
}

// ---------------- launch ----------------------------------------------------
extern "C" void kernel_launch(void* const* d_in, const int* in_sizes, int n_in,
                              void* d_out, int out_size) {
    const float* h      = (const float*)d_in[0];
    const int*   src    = (const int*)  d_in[1];
    const int*   dst    = (const int*)  d_in[2];
    const float* W      = (const float*)d_in[3];
    const float* attn_l = (const float*)d_in[4];
    const float* attn_r = (const float*)d_in[5];
    float* out = (float*)d_out;

    wlr_kernel    <<<1, 256>>>(W, attn_l, attn_r);
    gemm_kernel   <<<N_NODES / 16, 128>>>(h, W);
    elr_kernel    <<<(N_NODES * 32 + 255) / 256, 256>>>(h);
    hist_kernel   <<<(E_EDGES + 255) / 256, 256>>>(dst);
    scanA_kernel  <<<NPART, SCAN_BS>>>();
    scanB_kernel  <<<1, 256>>>();
    scanC_kernel  <<<NPART, SCAN_BS>>>();
    scatter_kernel<<<(E_EDGES + 255) / 256, 256>>>(src, dst);
    agg_kernel    <<<(N_NODES * 32 + 255) / 256, 256>>>(out);
}

// round 10
// speedup vs baseline: 1.0511x; 1.0511x over previous
#include <cuda_runtime.h>
#include <cuda_fp16.h>

#define N_NODES 100000
#define E_EDGES 1600000
#define D 128

#define GEMM_BLOCKS (N_NODES / 16)              // 6250
#define HIST_BLOCKS (E_EDGES / 256)             // 6250
#define K1_BLOCKS   (GEMM_BLOCKS + HIST_BLOCKS + 1)

// ---------------- scratch (static device globals; no runtime alloc) ---------
__device__ __half g_feat_h[N_NODES * D];  // projected features fp16 (25.6 MB)
__device__ float  g_wl[D];                // W @ attn_l
__device__ float  g_wr[D];                // W @ attn_r
__device__ float  g_el[N_NODES];          // src attention logits (fp32-exact)
__device__ float  g_er[N_NODES];          // dst attention logits
__device__ int    g_cnt[N_NODES];         // in-degree histogram (zeroed by scanC)
__device__ int    g_off[N_NODES + 1];     // CSR offsets (off[N]=E)
__device__ int    g_cur[N_NODES];         // scatter cursors
__device__ int2   g_sedge[E_EDGES];       // CSR slot: {src, exp-weight bits}

#define SCAN_BS 512
#define NPART ((N_NODES + SCAN_BS - 1) / SCAN_BS)   // 196
#define ELR_BLOCKS (N_NODES / 16)                   // 6250 (16 warps/block)
__device__ int g_part[NPART];
__device__ int g_pbase[NPART];

// ---------------- packed f32x2 helpers (sm_103a FFMA2) ----------------------
__device__ __forceinline__ unsigned long long pack2(float lo, float hi) {
    unsigned long long r;
    asm("mov.b64 %0, {%1,%2};" : "=l"(r) : "f"(lo), "f"(hi));
    return r;
}
__device__ __forceinline__ void unpack2(unsigned long long v, float& lo, float& hi) {
    asm("mov.b64 {%0,%1}, %2;" : "=f"(lo), "=f"(hi) : "l"(v));
}
__device__ __forceinline__ unsigned long long ffma2(unsigned long long a,
                                                    unsigned long long b,
                                                    unsigned long long c) {
    unsigned long long d;
    asm("fma.rn.f32x2 %0, %1, %2, %3;" : "=l"(d) : "l"(a), "l"(b), "l"(c));
    return d;
}
__device__ __forceinline__ float2 h2tof2(unsigned int u) {
    __half2 h;
    *reinterpret_cast<unsigned int*>(&h) = u;
    return __half22float2(h);
}

// ---------------- K1 mega: gemm | hist | wlr by block range -----------------
__global__ void __launch_bounds__(128)
mega1_kernel(const float* __restrict__ h, const float* __restrict__ W,
             const float* __restrict__ attn_l, const float* __restrict__ attn_r,
             const int* __restrict__ dst) {
    const int bid = blockIdx.x;
    const int t = threadIdx.x;

    if (bid < GEMM_BLOCKS) {
        // ---- gemm role: 16 rows, packed FFMA2 (identical to R6 gemm) ----
        __shared__ float4 hs4[D][4];
        const int row0 = bid * 16;
        {
            float tmp[16];
            #pragma unroll
            for (int r = 0; r < 16; r++)
                tmp[r] = h[(row0 + r) * D + t];
            #pragma unroll
            for (int q = 0; q < 4; q++)
                hs4[t][q] = make_float4(tmp[4*q], tmp[4*q+1], tmp[4*q+2], tmp[4*q+3]);
        }
        __syncthreads();

        unsigned long long acc2[8];
        #pragma unroll
        for (int j = 0; j < 8; j++) acc2[j] = 0ull;

        #pragma unroll 4
        for (int k = 0; k < D; k++) {
            const float wv = __ldg(&W[k * D + t]);
            const unsigned long long w2 = pack2(wv, wv);
            #pragma unroll
            for (int q = 0; q < 4; q++) {
                const float4 v = hs4[k][q];
                acc2[2*q]   = ffma2(pack2(v.x, v.y), w2, acc2[2*q]);
                acc2[2*q+1] = ffma2(pack2(v.z, v.w), w2, acc2[2*q+1]);
            }
        }

        #pragma unroll
        for (int j = 0; j < 8; j++) {
            float lo, hi;
            unpack2(acc2[j], lo, hi);
            g_feat_h[(row0 + 2*j)     * D + t] = __float2half(lo);
            g_feat_h[(row0 + 2*j + 1) * D + t] = __float2half(hi);
        }
    } else if (bid < GEMM_BLOCKS + HIST_BLOCKS) {
        // ---- hist role: 256 edges per block (LSU/L2, overlaps gemm FMA) ----
        const int e0 = (bid - GEMM_BLOCKS) * 256 + t;
        atomicAdd(&g_cnt[dst[e0]], 1);
        atomicAdd(&g_cnt[dst[e0 + 128]], 1);
    } else {
        // ---- wlr role: one block; thread t computes wl[t], wr[t] ----
        float sl = 0.f, sr = 0.f;
        #pragma unroll 8
        for (int j = 0; j < D; j++) {
            const float w = __ldg(&W[t * D + j]);
            sl = fmaf(w, __ldg(&attn_l[j]), sl);
            sr = fmaf(w, __ldg(&attn_r[j]), sr);
        }
        g_wl[t] = sl;
        g_wr[t] = sr;
    }
}

// ---------------- K2: scanA (per-part reduction) ----------------------------
__global__ void __launch_bounds__(SCAN_BS)
scanA_kernel() {
    __shared__ int sh[SCAN_BS];
    const int t = threadIdx.x;
    const int i = blockIdx.x * SCAN_BS + t;
    sh[t] = (i < N_NODES) ? g_cnt[i] : 0;
    __syncthreads();
    #pragma unroll
    for (int o = SCAN_BS / 2; o; o >>= 1) {
        if (t < o) sh[t] += sh[t + o];
        __syncthreads();
    }
    if (t == 0) g_part[blockIdx.x] = sh[0];
}

// ---------------- K3: scanB (partial prefix) --------------------------------
__global__ void __launch_bounds__(256)
scanB_kernel() {
    __shared__ int sh[256];
    const int t = threadIdx.x;
    const int v = (t < NPART) ? g_part[t] : 0;
    sh[t] = v;
    __syncthreads();
    for (int o = 1; o < 256; o <<= 1) {
        const int x = (t >= o) ? sh[t - o] : 0;
        __syncthreads();
        sh[t] += x;
        __syncthreads();
    }
    if (t < NPART) g_pbase[t] = sh[t] - v;       // exclusive
}

// ---------------- K4 merged: scanC | elr by block range ---------------------
__global__ void __launch_bounds__(SCAN_BS)
mega4_kernel(const float* __restrict__ h) {
    const int bid = blockIdx.x;
    const int t = threadIdx.x;

    if (bid < NPART) {
        // ---- scanC role: local exclusive scan + cursor init + cnt reset ----
        __shared__ int sh[SCAN_BS];
        const int i = bid * SCAN_BS + t;
        const int c = (i < N_NODES) ? g_cnt[i] : 0;
        sh[t] = c;
        __syncthreads();
        for (int o = 1; o < SCAN_BS; o <<= 1) {
            const int x = (t >= o) ? sh[t - o] : 0;
            __syncthreads();
            sh[t] += x;
            __syncthreads();
        }
        if (i < N_NODES) {
            const int off = g_pbase[bid] + sh[t] - c;   // exclusive
            g_off[i] = off;
            g_cur[i] = off;
            g_cnt[i] = 0;                   // restore invariant for next replay
        }
        if (bid == 0 && t == 0) g_off[N_NODES] = E_EDGES;
    } else {
        // ---- elr role: 16 warps, warp per node, fp32-exact ----
        const int warp = (bid - NPART) * 16 + (t >> 5);
        const int lane = t & 31;
        if (warp >= N_NODES) return;

        const float4 f  = __ldg(&reinterpret_cast<const float4*>(h)[warp * 32 + lane]);
        const float4 al = reinterpret_cast<const float4*>(g_wl)[lane];
        const float4 ar = reinterpret_cast<const float4*>(g_wr)[lane];
        float sl = f.x * al.x + f.y * al.y + f.z * al.z + f.w * al.w;
        float sr = f.x * ar.x + f.y * ar.y + f.z * ar.z + f.w * ar.w;
        #pragma unroll
        for (int o = 16; o; o >>= 1) {
            sl += __shfl_down_sync(0xffffffffu, sl, o);
            sr += __shfl_down_sync(0xffffffffu, sr, o);
        }
        if (lane == 0) { g_el[warp] = sl; g_er[warp] = sr; }
    }
}

// ---------------- K5: fused edge score + CSR scatter ------------------------
__global__ void __launch_bounds__(256)
scatter_kernel(const int* __restrict__ src, const int* __restrict__ dst) {
    const int e = blockIdx.x * blockDim.x + threadIdx.x;
    if (e >= E_EDGES) return;
    const int s = src[e];
    const int d = dst[e];
    float x = g_el[s] + g_er[d];
    x = (x > 0.f) ? x : 0.2f * x;            // leaky relu
    const float ex = __expf(x);              // |x| small: no max-shift needed
    const int idx = atomicAdd(&g_cur[d], 1);
    g_sedge[idx] = make_int2(s, __float_as_int(ex));
}

// ---------------- K6: aggregation — warp/node, lane-parallel edge fetch -----
__global__ void __launch_bounds__(256)
agg_kernel(float* __restrict__ out) {
    const int warp = (blockIdx.x * blockDim.x + threadIdx.x) >> 5;
    const int lane = threadIdx.x & 31;
    if (warp >= N_NODES) return;

    const int beg = g_off[warp];
    const int end = g_off[warp + 1];

    const uint2* __restrict__ featv = reinterpret_cast<const uint2*>(g_feat_h);

    float4 acc = make_float4(0.f, 0.f, 0.f, 0.f);
    float den = 0.f;

    for (int base = beg; base < end; base += 32) {
        const int n = min(32, end - base);
        // whole warp's edge chunk: 1-2 cache lines, one lane-parallel load
        int2 p = (lane < n) ? g_sedge[base + lane] : make_int2(0, 0);
        int c = 0;
        for (; c + 4 <= n; c += 4) {
            const int   s0 = __shfl_sync(0xffffffffu, p.x, c);
            const float w0 = __int_as_float(__shfl_sync(0xffffffffu, p.y, c));
            const int   s1 = __shfl_sync(0xffffffffu, p.x, c + 1);
            const float w1 = __int_as_float(__shfl_sync(0xffffffffu, p.y, c + 1));
            const int   s2 = __shfl_sync(0xffffffffu, p.x, c + 2);
            const float w2 = __int_as_float(__shfl_sync(0xffffffffu, p.y, c + 2));
            const int   s3 = __shfl_sync(0xffffffffu, p.x, c + 3);
            const float w3 = __int_as_float(__shfl_sync(0xffffffffu, p.y, c + 3));
            const uint2 v0 = __ldg(&featv[s0 * 32 + lane]);
            const uint2 v1 = __ldg(&featv[s1 * 32 + lane]);
            const uint2 v2 = __ldg(&featv[s2 * 32 + lane]);
            const uint2 v3 = __ldg(&featv[s3 * 32 + lane]);
            den += (w0 + w1) + (w2 + w3);
            const float2 a0 = h2tof2(v0.x), b0 = h2tof2(v0.y);
            const float2 a1 = h2tof2(v1.x), b1 = h2tof2(v1.y);
            const float2 a2 = h2tof2(v2.x), b2 = h2tof2(v2.y);
            const float2 a3 = h2tof2(v3.x), b3 = h2tof2(v3.y);
            acc.x = fmaf(w0, a0.x, acc.x); acc.y = fmaf(w0, a0.y, acc.y);
            acc.z = fmaf(w0, b0.x, acc.z); acc.w = fmaf(w0, b0.y, acc.w);
            acc.x = fmaf(w1, a1.x, acc.x); acc.y = fmaf(w1, a1.y, acc.y);
            acc.z = fmaf(w1, b1.x, acc.z); acc.w = fmaf(w1, b1.y, acc.w);
            acc.x = fmaf(w2, a2.x, acc.x); acc.y = fmaf(w2, a2.y, acc.y);
            acc.z = fmaf(w2, b2.x, acc.z); acc.w = fmaf(w2, b2.y, acc.w);
            acc.x = fmaf(w3, a3.x, acc.x); acc.y = fmaf(w3, a3.y, acc.y);
            acc.z = fmaf(w3, b3.x, acc.z); acc.w = fmaf(w3, b3.y, acc.w);
        }
        for (; c < n; c++) {
            const int   s = __shfl_sync(0xffffffffu, p.x, c);
            const float w = __int_as_float(__shfl_sync(0xffffffffu, p.y, c));
            const uint2 v = __ldg(&featv[s * 32 + lane]);
            den += w;
            const float2 a = h2tof2(v.x), b = h2tof2(v.y);
            acc.x = fmaf(w, a.x, acc.x); acc.y = fmaf(w, a.y, acc.y);
            acc.z = fmaf(w, b.x, acc.z); acc.w = fmaf(w, b.y, acc.w);
        }
    }
    const float inv = 1.f / fmaxf(den, 1e-9f);
    acc.x *= inv; acc.y *= inv; acc.z *= inv; acc.w *= inv;
    reinterpret_cast<float4*>(out)[warp * 32 + lane] = acc;
}

// ---------------- launch: 6 kernels, single stream --------------------------
extern "C" void kernel_launch(void* const* d_in, const int* in_sizes, int n_in,
                              void* d_out, int out_size) {
    const float* h      = (const float*)d_in[0];
    const int*   src    = (const int*)  d_in[1];
    const int*   dst    = (const int*)  d_in[2];
    const float* W      = (const float*)d_in[3];
    const float* attn_l = (const float*)d_in[4];
    const float* attn_r = (const float*)d_in[5];
    float* out = (float*)d_out;

    mega1_kernel  <<<K1_BLOCKS, 128>>>(h, W, attn_l, attn_r, dst);
    scanA_kernel  <<<NPART, SCAN_BS>>>();
    scanB_kernel  <<<1, 256>>>();
    mega4_kernel  <<<NPART + ELR_BLOCKS, SCAN_BS>>>(h);
    scatter_kernel<<<(E_EDGES + 255) / 256, 256>>>(src, dst);
    agg_kernel    <<<(N_NODES * 32 + 255) / 256, 256>>>(out);
}

// round 13
// speedup vs baseline: 1.2337x; 1.1737x over previous
#include <cuda_runtime.h>
#include <cuda_fp16.h>
#include <mma.h>
using namespace nvcuda;

#define N_NODES 100000
#define E_EDGES 1600000
#define D 128

#define GEMM_BLOCKS ((N_NODES + 127) / 128)     // 782  (128 rows/block)
#define HIST_BLOCKS (E_EDGES / 512)             // 3125 (512 edges/block)
#define K1_BLOCKS   (GEMM_BLOCKS + HIST_BLOCKS + 1)

// ---------------- scratch (static device globals; no runtime alloc) ---------
__device__ __half g_feat_h[N_NODES * D];  // projected features fp16 (25.6 MB)
__device__ float  g_wl[D];                // W @ attn_l
__device__ float  g_wr[D];                // W @ attn_r
__device__ float  g_el[N_NODES];          // src attention logits (fp32-exact)
__device__ float  g_er[N_NODES];          // dst attention logits
__device__ int    g_cnt[N_NODES];         // in-degree histogram (zeroed by scanC)
__device__ int    g_off[N_NODES + 1];     // CSR offsets (off[N]=E)
__device__ int    g_cur[N_NODES];         // scatter cursors
__device__ int2   g_sedge[E_EDGES];       // CSR slot: {src, exp-weight bits}

#define SCAN_BS 512
#define NPART ((N_NODES + SCAN_BS - 1) / SCAN_BS)   // 196
#define ELR_BLOCKS (N_NODES / 16)                   // 6250 (16 warps/block)
__device__ int g_part[NPART];
__device__ int g_pbase[NPART];

__device__ __forceinline__ float2 h2tof2(unsigned int u) {
    __half2 h;
    *reinterpret_cast<unsigned int*>(&h) = u;
    return __half22float2(h);
}

// ---------------- K1 mega: wmma gemm | hist | wlr by block range ------------
__global__ void __launch_bounds__(256)
mega1_kernel(const float* __restrict__ h, const float* __restrict__ W,
             const float* __restrict__ attn_l, const float* __restrict__ attn_r,
             const int* __restrict__ dst) {
    const int bid = blockIdx.x;
    const int t = threadIdx.x;

    if (bid < GEMM_BLOCKS) {
        // ---- gemm role: 128x128x128 tile, fp16 HMMA, fp32 accumulate ----
        __shared__ __half sa[128 * 32];     // A tile [128][32]           8 KB
        __shared__ __half sb[32 * 128];     // B tile [32][128]           8 KB
        __shared__ float  sepi[8 * 256];    // per-warp 16x16 staging     8 KB

        const int row0 = bid * 128;
        const int w    = t >> 5;            // warp 0..7
        const int lane = t & 31;
        const int wm   = w >> 1;            // 0..3 (32-row strip)
        const int wn   = w & 1;             // 0..1 (64-col strip)

        wmma::fragment<wmma::accumulator, 16, 16, 16, float> fc[2][4];
        #pragma unroll
        for (int i = 0; i < 2; i++)
            #pragma unroll
            for (int j = 0; j < 4; j++)
                wmma::fill_fragment(fc[i][j], 0.0f);

        #pragma unroll
        for (int k0 = 0; k0 < 4; k0++) {    // K chunks of 32
            // load A: rows row0..row0+127, cols k0*32..+32 (fp32 -> fp16)
            #pragma unroll
            for (int p = 0; p < 4; p++) {
                const int r  = p * 32 + (t >> 3);
                const int cg = t & 7;
                int grow = row0 + r;
                if (grow >= N_NODES) grow = 0;      // junk rows, stores guarded
                const float4 v = __ldg(reinterpret_cast<const float4*>(
                                           h + grow * D + k0 * 32) + cg);
                __half2* dp = reinterpret_cast<__half2*>(&sa[r * 32 + cg * 4]);
                dp[0] = __floats2half2_rn(v.x, v.y);
                dp[1] = __floats2half2_rn(v.z, v.w);
            }
            // load B: W rows k0*32..+32, all 128 cols (fp32 -> fp16)
            #pragma unroll
            for (int p = 0; p < 4; p++) {
                const int idx4 = p * 256 + t;       // 0..1023 float4s
                const int r  = idx4 >> 5;
                const int cg = idx4 & 31;
                const float4 v = __ldg(reinterpret_cast<const float4*>(
                                           W + (k0 * 32 + r) * D) + cg);
                __half2* dp = reinterpret_cast<__half2*>(&sb[r * 128 + cg * 4]);
                dp[0] = __floats2half2_rn(v.x, v.y);
                dp[1] = __floats2half2_rn(v.z, v.w);
            }
            __syncthreads();

            #pragma unroll
            for (int kk = 0; kk < 32; kk += 16) {
                wmma::fragment<wmma::matrix_a, 16, 16, 16, __half, wmma::row_major> fa0, fa1;
                wmma::load_matrix_sync(fa0, &sa[(wm * 32)      * 32 + kk], 32);
                wmma::load_matrix_sync(fa1, &sa[(wm * 32 + 16) * 32 + kk], 32);
                #pragma unroll
                for (int j = 0; j < 4; j++) {
                    wmma::fragment<wmma::matrix_b, 16, 16, 16, __half, wmma::row_major> fb;
                    wmma::load_matrix_sync(fb, &sb[kk * 128 + wn * 64 + j * 16], 128);
                    wmma::mma_sync(fc[0][j], fa0, fb, fc[0][j]);
                    wmma::mma_sync(fc[1][j], fa1, fb, fc[1][j]);
                }
            }
            __syncthreads();
        }

        // epilogue: per-warp 16x16 staging -> fp16 global (STG.128)
        float* ep = &sepi[w * 256];
        #pragma unroll
        for (int i = 0; i < 2; i++) {
            #pragma unroll
            for (int j = 0; j < 4; j++) {
                wmma::store_matrix_sync(ep, fc[i][j], 16, wmma::mem_row_major);
                __syncwarp();
                const int rr = lane >> 1;
                const int cc = (lane & 1) * 8;
                const int grow = row0 + wm * 32 + i * 16 + rr;
                if (grow < N_NODES) {
                    const float* sp = &ep[rr * 16 + cc];
                    __half2 q0 = __floats2half2_rn(sp[0], sp[1]);
                    __half2 q1 = __floats2half2_rn(sp[2], sp[3]);
                    __half2 q2 = __floats2half2_rn(sp[4], sp[5]);
                    __half2 q3 = __floats2half2_rn(sp[6], sp[7]);
                    uint4 pk;
                    pk.x = *reinterpret_cast<unsigned*>(&q0);
                    pk.y = *reinterpret_cast<unsigned*>(&q1);
                    pk.z = *reinterpret_cast<unsigned*>(&q2);
                    pk.w = *reinterpret_cast<unsigned*>(&q3);
                    *reinterpret_cast<uint4*>(
                        &g_feat_h[grow * D + wn * 64 + j * 16 + cc]) = pk;
                }
                __syncwarp();
            }
        }
    } else if (bid < GEMM_BLOCKS + HIST_BLOCKS) {
        // ---- hist role: 512 edges per block ----
        const int e0 = (bid - GEMM_BLOCKS) * 512 + t;
        atomicAdd(&g_cnt[dst[e0]], 1);
        atomicAdd(&g_cnt[dst[e0 + 256]], 1);
    } else {
        // ---- wlr role: one block; wl[k]=sum_n W[k][n]*attn_l[n] ----
        const int k = t & 127;
        const float* v = (t < 128) ? attn_l : attn_r;
        float s = 0.f;
        #pragma unroll 8
        for (int j = 0; j < D; j++)
            s = fmaf(__ldg(&W[k * D + j]), __ldg(&v[j]), s);
        if (t < 128) g_wl[k] = s; else g_wr[k] = s;
    }
}

// ---------------- K2: scanA (per-part reduction) ----------------------------
__global__ void __launch_bounds__(SCAN_BS)
scanA_kernel() {
    __shared__ int sh[SCAN_BS];
    const int t = threadIdx.x;
    const int i = blockIdx.x * SCAN_BS + t;
    sh[t] = (i < N_NODES) ? g_cnt[i] : 0;
    __syncthreads();
    #pragma unroll
    for (int o = SCAN_BS / 2; o; o >>= 1) {
        if (t < o) sh[t] += sh[t + o];
        __syncthreads();
    }
    if (t == 0) g_part[blockIdx.x] = sh[0];
}

// ---------------- K3: scanB (partial prefix) --------------------------------
__global__ void __launch_bounds__(256)
scanB_kernel() {
    __shared__ int sh[256];
    const int t = threadIdx.x;
    const int v = (t < NPART) ? g_part[t] : 0;
    sh[t] = v;
    __syncthreads();
    for (int o = 1; o < 256; o <<= 1) {
        const int x = (t >= o) ? sh[t - o] : 0;
        __syncthreads();
        sh[t] += x;
        __syncthreads();
    }
    if (t < NPART) g_pbase[t] = sh[t] - v;       // exclusive
}

// ---------------- K4 merged: scanC | elr by block range ---------------------
__global__ void __launch_bounds__(SCAN_BS)
mega4_kernel(const float* __restrict__ h) {
    const int bid = blockIdx.x;
    const int t = threadIdx.x;

    if (bid < NPART) {
        // ---- scanC role: local exclusive scan + cursor init + cnt reset ----
        __shared__ int sh[SCAN_BS];
        const int i = bid * SCAN_BS + t;
        const int c = (i < N_NODES) ? g_cnt[i] : 0;
        sh[t] = c;
        __syncthreads();
        for (int o = 1; o < SCAN_BS; o <<= 1) {
            const int x = (t >= o) ? sh[t - o] : 0;
            __syncthreads();
            sh[t] += x;
            __syncthreads();
        }
        if (i < N_NODES) {
            const int off = g_pbase[bid] + sh[t] - c;   // exclusive
            g_off[i] = off;
            g_cur[i] = off;
            g_cnt[i] = 0;                   // restore invariant for next replay
        }
        if (bid == 0 && t == 0) g_off[N_NODES] = E_EDGES;
    } else {
        // ---- elr role: 16 warps, warp per node, fp32-exact ----
        const int warp = (bid - NPART) * 16 + (t >> 5);
        const int lane = t & 31;
        if (warp >= N_NODES) return;

        const float4 f  = __ldg(&reinterpret_cast<const float4*>(h)[warp * 32 + lane]);
        const float4 al = reinterpret_cast<const float4*>(g_wl)[lane];
        const float4 ar = reinterpret_cast<const float4*>(g_wr)[lane];
        float sl = f.x * al.x + f.y * al.y + f.z * al.z + f.w * al.w;
        float sr = f.x * ar.x + f.y * ar.y + f.z * ar.z + f.w * ar.w;
        #pragma unroll
        for (int o = 16; o; o >>= 1) {
            sl += __shfl_down_sync(0xffffffffu, sl, o);
            sr += __shfl_down_sync(0xffffffffu, sr, o);
        }
        if (lane == 0) { g_el[warp] = sl; g_er[warp] = sr; }
    }
}

// ---------------- K5: fused edge score + CSR scatter ------------------------
__global__ void __launch_bounds__(256)
scatter_kernel(const int* __restrict__ src, const int* __restrict__ dst) {
    const int e = blockIdx.x * blockDim.x + threadIdx.x;
    if (e >= E_EDGES) return;
    const int s = src[e];
    const int d = dst[e];
    float x = g_el[s] + g_er[d];
    x = (x > 0.f) ? x : 0.2f * x;            // leaky relu
    const float ex = __expf(x);              // |x| small: no max-shift needed
    const int idx = atomicAdd(&g_cur[d], 1);
    g_sedge[idx] = make_int2(s, __float_as_int(ex));
}

// ---------------- K6: aggregation — warp/node, lane-parallel edge fetch -----
__global__ void __launch_bounds__(256)
agg_kernel(float* __restrict__ out) {
    const int warp = (blockIdx.x * blockDim.x + threadIdx.x) >> 5;
    const int lane = threadIdx.x & 31;
    if (warp >= N_NODES) return;

    const int beg = g_off[warp];
    const int end = g_off[warp + 1];

    const uint2* __restrict__ featv = reinterpret_cast<const uint2*>(g_feat_h);

    float4 acc = make_float4(0.f, 0.f, 0.f, 0.f);
    float den = 0.f;

    for (int base = beg; base < end; base += 32) {
        const int n = min(32, end - base);
        int2 p = (lane < n) ? g_sedge[base + lane] : make_int2(0, 0);
        int c = 0;
        for (; c + 4 <= n; c += 4) {
            const int   s0 = __shfl_sync(0xffffffffu, p.x, c);
            const float w0 = __int_as_float(__shfl_sync(0xffffffffu, p.y, c));
            const int   s1 = __shfl_sync(0xffffffffu, p.x, c + 1);
            const float w1 = __int_as_float(__shfl_sync(0xffffffffu, p.y, c + 1));
            const int   s2 = __shfl_sync(0xffffffffu, p.x, c + 2);
            const float w2 = __int_as_float(__shfl_sync(0xffffffffu, p.y, c + 2));
            const int   s3 = __shfl_sync(0xffffffffu, p.x, c + 3);
            const float w3 = __int_as_float(__shfl_sync(0xffffffffu, p.y, c + 3));
            const uint2 v0 = __ldg(&featv[s0 * 32 + lane]);
            const uint2 v1 = __ldg(&featv[s1 * 32 + lane]);
            const uint2 v2 = __ldg(&featv[s2 * 32 + lane]);
            const uint2 v3 = __ldg(&featv[s3 * 32 + lane]);
            den += (w0 + w1) + (w2 + w3);
            const float2 a0 = h2tof2(v0.x), b0 = h2tof2(v0.y);
            const float2 a1 = h2tof2(v1.x), b1 = h2tof2(v1.y);
            const float2 a2 = h2tof2(v2.x), b2 = h2tof2(v2.y);
            const float2 a3 = h2tof2(v3.x), b3 = h2tof2(v3.y);
            acc.x = fmaf(w0, a0.x, acc.x); acc.y = fmaf(w0, a0.y, acc.y);
            acc.z = fmaf(w0, b0.x, acc.z); acc.w = fmaf(w0, b0.y, acc.w);
            acc.x = fmaf(w1, a1.x, acc.x); acc.y = fmaf(w1, a1.y, acc.y);
            acc.z = fmaf(w1, b1.x, acc.z); acc.w = fmaf(w1, b1.y, acc.w);
            acc.x = fmaf(w2, a2.x, acc.x); acc.y = fmaf(w2, a2.y, acc.y);
            acc.z = fmaf(w2, b2.x, acc.z); acc.w = fmaf(w2, b2.y, acc.w);
            acc.x = fmaf(w3, a3.x, acc.x); acc.y = fmaf(w3, a3.y, acc.y);
            acc.z = fmaf(w3, b3.x, acc.z); acc.w = fmaf(w3, b3.y, acc.w);
        }
        for (; c < n; c++) {
            const int   s = __shfl_sync(0xffffffffu, p.x, c);
            const float w = __int_as_float(__shfl_sync(0xffffffffu, p.y, c));
            const uint2 v = __ldg(&featv[s * 32 + lane]);
            den += w;
            const float2 a = h2tof2(v.x), b = h2tof2(v.y);
            acc.x = fmaf(w, a.x, acc.x); acc.y = fmaf(w, a.y, acc.y);
            acc.z = fmaf(w, b.x, acc.z); acc.w = fmaf(w, b.y, acc.w);
        }
    }
    const float inv = 1.f / fmaxf(den, 1e-9f);
    acc.x *= inv; acc.y *= inv; acc.z *= inv; acc.w *= inv;
    reinterpret_cast<float4*>(out)[warp * 32 + lane] = acc;
}

// ---------------- launch: 6 kernels, single stream --------------------------
extern "C" void kernel_launch(void* const* d_in, const int* in_sizes, int n_in,
                              void* d_out, int out_size) {
    const float* h      = (const float*)d_in[0];
    const int*   src    = (const int*)  d_in[1];
    const int*   dst    = (const int*)  d_in[2];
    const float* W      = (const float*)d_in[3];
    const float* attn_l = (const float*)d_in[4];
    const float* attn_r = (const float*)d_in[5];
    float* out = (float*)d_out;

    mega1_kernel  <<<K1_BLOCKS, 256>>>(h, W, attn_l, attn_r, dst);
    scanA_kernel  <<<NPART, SCAN_BS>>>();
    scanB_kernel  <<<1, 256>>>();
    mega4_kernel  <<<NPART + ELR_BLOCKS, SCAN_BS>>>(h);
    scatter_kernel<<<(E_EDGES + 255) / 256, 256>>>(src, dst);
    agg_kernel    <<<(N_NODES * 32 + 255) / 256, 256>>>(out);
}